// round 7
// baseline (speedup 1.0000x reference)
#include <cuda_runtime.h>

// ---------------------------------------------------------------------------
// MNIST TWN CNN forward, batch 4096, fp32.
// R7: conv2 — replicated u64 input (no rep2 MOVs), padded weight rows
//     (LDS.128), 4-ci weight groups (16 barriers), 2 img/CTA dynamic smem.
//     bnpool2 fused into fc1 A-tile load.
// Launches: absmax, conv1, fin1, conv2(#4 profiled), fc1, fc2.
// ---------------------------------------------------------------------------

#define NIMG 4096
typedef unsigned long long u64;

__device__ __forceinline__ u64 pack2(float lo, float hi) {
    u64 r; asm("mov.b64 %0,{%1,%2};" : "=l"(r) : "f"(lo), "f"(hi)); return r;
}
__device__ __forceinline__ u64 rep2(float v) { return pack2(v, v); }
__device__ __forceinline__ void unpack2(u64 p, float& lo, float& hi) {
    asm("mov.b64 {%0,%1},%2;" : "=f"(lo), "=f"(hi) : "l"(p));
}
__device__ __forceinline__ void ffma2(u64& d, u64 a, u64 b) {
    asm("fma.rn.f32x2 %0,%1,%2,%0;" : "+l"(d) : "l"(a), "l"(b));
}
__device__ __forceinline__ u64 add2(u64 a, u64 b) {
    u64 r; asm("add.rn.f32x2 %0,%1,%2;" : "=l"(r) : "l"(a), "l"(b)); return r;
}
__device__ __forceinline__ float ternary(float w, float t) {
    return (w > t ? 1.0f : 0.0f) - (w < -t ? 1.0f : 0.0f);
}
__device__ __forceinline__ float bnsel(float A, float B, float mx, float mn) {
    return fmaxf(A > 0.f ? fmaf(A, mx, B) : fmaf(A, mn, B), 0.f);
}

// ---- device scratch (static only) -----------------------------------------
// conv2 weights: [ci][pc][5 rows x 6 (5 taps + pad)] u64 channel pairs.
static __device__ u64   g_w2p[32 * 32 * 30];
static __device__ float g_wf1q[512 * 1024];
static __device__ float g_wf2q[10 * 512];
static __device__ float g_pmax[96][4];

static __device__ double g_sum1[32],  g_sqs1[32];
static __device__ double g_sum2[64],  g_sqs2[64];
static __device__ double g_sum3[512], g_sqs3[512];

static __device__ float g_sc1[32], g_sh1[32];

static __device__ float g_m1max[NIMG * 32 * 144];
static __device__ float g_m1min[NIMG * 32 * 144];
static __device__ float g_m2max[NIMG * 1024];
static __device__ float g_m2min[NIMG * 1024];
static __device__ float g_y3[NIMG * 512];

// ---------------------------------------------------------------------------
// Launch 1: abs-max partials (grid MUST be 96). Block 0 zeros stat accums.
// ---------------------------------------------------------------------------
__global__ __launch_bounds__(256) void k_absmax(const float* __restrict__ w1, const float* __restrict__ w2,
                                                const float* __restrict__ wf1, const float* __restrict__ wf2) {
    __shared__ float sm[8][4];
    int tid = threadIdx.x;
    if (blockIdx.x == 0) {
        if (tid < 32) { g_sum1[tid] = 0.0; g_sqs1[tid] = 0.0; }
        if (tid < 64) { g_sum2[tid] = 0.0; g_sqs2[tid] = 0.0; }
        g_sum3[tid] = 0.0;       g_sqs3[tid] = 0.0;
        g_sum3[tid + 256] = 0.0; g_sqs3[tid + 256] = 0.0;
    }
    int gid = blockIdx.x * 256 + tid;
    int stride = 96 * 256;
    float m0 = 0.f, m1 = 0.f, m2 = 0.f, m3 = 0.f;
    for (int i = gid; i < 800;    i += stride) m0 = fmaxf(m0, fabsf(w1[i]));
    for (int i = gid; i < 51200;  i += stride) m1 = fmaxf(m1, fabsf(w2[i]));
    for (int i = gid; i < 524288; i += stride) m2 = fmaxf(m2, fabsf(wf1[i]));
    for (int i = gid; i < 5120;   i += stride) m3 = fmaxf(m3, fabsf(wf2[i]));
    #pragma unroll
    for (int off = 16; off; off >>= 1) {
        m0 = fmaxf(m0, __shfl_xor_sync(0xffffffffu, m0, off));
        m1 = fmaxf(m1, __shfl_xor_sync(0xffffffffu, m1, off));
        m2 = fmaxf(m2, __shfl_xor_sync(0xffffffffu, m2, off));
        m3 = fmaxf(m3, __shfl_xor_sync(0xffffffffu, m3, off));
    }
    int w = tid >> 5;
    if ((tid & 31) == 0) { sm[w][0] = m0; sm[w][1] = m1; sm[w][2] = m2; sm[w][3] = m3; }
    __syncthreads();
    if (tid == 0) {
        float r0 = 0.f, r1 = 0.f, r2 = 0.f, r3 = 0.f;
        #pragma unroll
        for (int i = 0; i < 8; i++) {
            r0 = fmaxf(r0, sm[i][0]); r1 = fmaxf(r1, sm[i][1]);
            r2 = fmaxf(r2, sm[i][2]); r3 = fmaxf(r3, sm[i][3]);
        }
        g_pmax[blockIdx.x][0] = r0; g_pmax[blockIdx.x][1] = r1;
        g_pmax[blockIdx.x][2] = r2; g_pmax[blockIdx.x][3] = r3;
    }
}

// ---------------------------------------------------------------------------
// Launch 2: conv1 + stats + pooled max/min. One block/image, 192 threads.
// ---------------------------------------------------------------------------
__global__ __launch_bounds__(192) void k_conv1(const float* __restrict__ x,  const float* __restrict__ w1,
                                               const float* __restrict__ w2, const float* __restrict__ wf1,
                                               const float* __restrict__ wf2) {
    __shared__ u64 sx[784];
    __shared__ u64 sw1[400];
    __shared__ float sthr[4];
    __shared__ float ssum[32], ssq[32];
    int tid = threadIdx.x, n = blockIdx.x;

    if (tid < 4) {
        float m = 0.f;
        #pragma unroll 8
        for (int i = 0; i < 96; i++) m = fmaxf(m, g_pmax[i][tid]);
        sthr[tid] = 0.05f * m;
    }
    if (tid < 32) { ssum[tid] = 0.f; ssq[tid] = 0.f; }
    __syncthreads();

    for (int i = tid; i < 400; i += 192) {
        int cp = i / 25, k = i - cp * 25;
        float t0 = sthr[0];
        sw1[i] = pack2(ternary(w1[(2 * cp) * 25 + k], t0),
                       ternary(w1[(2 * cp + 1) * 25 + k], t0));
    }
    for (int i = tid; i < 784; i += 192) sx[i] = rep2(x[n * 784 + i]);

    {   // distributed quantization (padded conv2 layout)
        int gu = n * 192 + tid;
        if (gu < 25600) {
            int ci = gu / 800, r = gu - ci * 800;
            int pc = r / 25, k = r - pc * 25;
            float t1 = sthr[1];
            int off = ci * 960 + pc * 30 + (k / 5) * 6 + (k % 5);
            ((float2*)g_w2p)[off] = make_float2(ternary(w2[(2 * pc) * 800 + ci * 25 + k], t1),
                                                ternary(w2[(2 * pc + 1) * 800 + ci * 25 + k], t1));
        } else if (gu < 25600 + 524288) {
            g_wf1q[gu - 25600] = ternary(wf1[gu - 25600], sthr[2]);
        } else if (gu < 25600 + 524288 + 5120) {
            g_wf2q[gu - 549888] = ternary(wf2[gu - 549888], sthr[3]);
        }
    }
    __syncthreads();

    int cp = tid / 12;
    int q  = tid - cp * 12;
    const u64* wbase = sw1 + cp * 25;
    u64 sp = 0ull, qp = 0ull;
    float* pmx0 = g_m1max + n * 4608 + (2 * cp) * 144 + q * 12;
    float* pmn0 = g_m1min + n * 4608 + (2 * cp) * 144 + q * 12;

    #pragma unroll
    for (int ob = 0; ob < 24; ob += 4) {
        u64 a0[4] = {0ull, 0ull, 0ull, 0ull};
        u64 a1[4] = {0ull, 0ull, 0ull, 0ull};
        u64 pw0, pw1, pw2, pw3, pw4;
        pw0 = pw1 = pw2 = pw3 = pw4 = 0ull;
        #pragma unroll
        for (int rr = 0; rr < 6; rr++) {
            const ulonglong2* xr = (const ulonglong2*)(sx + (2 * q + rr) * 28 + ob);
            ulonglong2 v0 = xr[0], v1 = xr[1], v2 = xr[2], v3 = xr[3];
            u64 X[8] = { v0.x, v0.y, v1.x, v1.y, v2.x, v2.y, v3.x, v3.y };
            if (rr >= 1) {
                #pragma unroll
                for (int o = 0; o < 4; o++) {
                    ffma2(a1[o], X[o],     pw0);
                    ffma2(a1[o], X[o + 1], pw1);
                    ffma2(a1[o], X[o + 2], pw2);
                    ffma2(a1[o], X[o + 3], pw3);
                    ffma2(a1[o], X[o + 4], pw4);
                }
            }
            if (rr < 5) {
                const u64* wr = wbase + rr * 5;
                u64 c0 = wr[0], c1 = wr[1], c2 = wr[2], c3 = wr[3], c4 = wr[4];
                #pragma unroll
                for (int o = 0; o < 4; o++) {
                    ffma2(a0[o], X[o],     c0);
                    ffma2(a0[o], X[o + 1], c1);
                    ffma2(a0[o], X[o + 2], c2);
                    ffma2(a0[o], X[o + 3], c3);
                    ffma2(a0[o], X[o + 4], c4);
                }
                pw0 = c0; pw1 = c1; pw2 = c2; pw3 = c3; pw4 = c4;
            }
        }
        float r0c0[4], r0c1[4], r1c0[4], r1c1[4];
        #pragma unroll
        for (int o = 0; o < 4; o++) {
            sp = add2(sp, a0[o]); ffma2(qp, a0[o], a0[o]);
            sp = add2(sp, a1[o]); ffma2(qp, a1[o], a1[o]);
            unpack2(a0[o], r0c0[o], r0c1[o]);
            unpack2(a1[o], r1c0[o], r1c1[o]);
        }
        float mx0[2], mn0[2], mx1[2], mn1[2];
        #pragma unroll
        for (int j = 0; j < 2; j++) {
            float A0 = r0c0[2 * j], B0 = r0c0[2 * j + 1], C0 = r1c0[2 * j], D0 = r1c0[2 * j + 1];
            mx0[j] = fmaxf(fmaxf(A0, B0), fmaxf(C0, D0));
            mn0[j] = fminf(fminf(A0, B0), fminf(C0, D0));
            float A1 = r0c1[2 * j], B1 = r0c1[2 * j + 1], C1 = r1c1[2 * j], D1 = r1c1[2 * j + 1];
            mx1[j] = fmaxf(fmaxf(A1, B1), fmaxf(C1, D1));
            mn1[j] = fminf(fminf(A1, B1), fminf(C1, D1));
        }
        int pc2 = ob >> 1;
        *(float2*)(pmx0 + pc2)       = make_float2(mx0[0], mx0[1]);
        *(float2*)(pmn0 + pc2)       = make_float2(mn0[0], mn0[1]);
        *(float2*)(pmx0 + 144 + pc2) = make_float2(mx1[0], mx1[1]);
        *(float2*)(pmn0 + 144 + pc2) = make_float2(mn1[0], mn1[1]);
    }
    float s0, s1, q0, q1;
    unpack2(sp, s0, s1);
    unpack2(qp, q0, q1);
    atomicAdd(&ssum[2 * cp],     s0);
    atomicAdd(&ssum[2 * cp + 1], s1);
    atomicAdd(&ssq[2 * cp],      q0);
    atomicAdd(&ssq[2 * cp + 1],  q1);
    __syncthreads();
    if (tid < 32) {
        atomicAdd(&g_sum1[tid], (double)ssum[tid]);
        atomicAdd(&g_sqs1[tid], (double)ssq[tid]);
    }
}

// ---------------------------------------------------------------------------
// Launch 3: finalize layer-1 BN affine.
// ---------------------------------------------------------------------------
__global__ void k_fin1(const float* __restrict__ g, const float* __restrict__ be) {
    int i = threadIdx.x;
    if (i >= 32) return;
    const double invM = 1.0 / (4096.0 * 576.0);
    double mean = g_sum1[i] * invM;
    double var  = g_sqs1[i] * invM - mean * mean;
    float A = g[i] * rsqrtf((float)var + 1e-5f);
    g_sc1[i] = A;
    g_sh1[i] = be[i] - (float)mean * A;
}

// ---------------------------------------------------------------------------
// Launch 4 (PROFILED): conv2. Replicated u64 input in dynamic SMEM (no MOVs),
// weights in 4-ci groups with padded rows (LDS.128). 2 img/CTA, 256 thr.
// ---------------------------------------------------------------------------
extern __shared__ u64 s_dyn[];
__global__ __launch_bounds__(256) void k_conv2() {
    u64* sin2 = s_dyn;                 // 2 x 4608 u64 = 73.7 KB
    u64* swt  = s_dyn + 9216;          // 4 x 960 u64  = 30.7 KB
    __shared__ float sA1[32], sB1[32];
    int tid = threadIdx.x;
    int n0 = blockIdx.x * 2;

    if (tid < 32) { sA1[tid] = g_sc1[tid]; sB1[tid] = g_sh1[tid]; }
    __syncthreads();

    {   // staged load: bnsel + replicate
        const float4* mx4 = (const float4*)(g_m1max + n0 * 4608);
        const float4* mn4 = (const float4*)(g_m1min + n0 * 4608);
        for (int i = tid; i < 2304; i += 256) {
            int c = (i % 1152) / 36;
            float A = sA1[c], B = sB1[c];
            float4 mx = mx4[i], mn = mn4[i];
            ulonglong2 lo, hi;
            lo.x = rep2(bnsel(A, B, mx.x, mn.x));
            lo.y = rep2(bnsel(A, B, mx.y, mn.y));
            hi.x = rep2(bnsel(A, B, mx.z, mn.z));
            hi.y = rep2(bnsel(A, B, mx.w, mn.w));
            ((ulonglong2*)(sin2 + i * 4))[0] = lo;
            ((ulonglong2*)(sin2 + i * 4))[1] = hi;
        }
    }

    int img = tid >> 7;
    int t   = tid & 127;
    int pc  = t >> 2;                  // channel pair (2pc, 2pc+1)
    int q   = t & 3;                   // output rows 2q, 2q+1
    const u64* ib = sin2 + img * 4608 + q * 24;

    u64 acc[2][8];
    #pragma unroll
    for (int oy = 0; oy < 2; oy++)
        #pragma unroll
        for (int px = 0; px < 8; px++) acc[oy][px] = 0ull;

    for (int g = 0; g < 8; g++) {
        __syncthreads();               // protect swt (also covers initial sin2 fill)
        const ulonglong2* wsg = (const ulonglong2*)(g_w2p + g * 3840);
        ulonglong2* wdst = (ulonglong2*)swt;
        for (int i = tid; i < 1920; i += 256) wdst[i] = wsg[i];
        __syncthreads();
        #pragma unroll
        for (int cc = 0; cc < 4; cc++) {
            int ci = g * 4 + cc;
            const u64* wp = swt + cc * 960 + pc * 30;
            const u64* rb = ib + ci * 144;
            u64 pw0, pw1, pw2, pw3, pw4;
            pw0 = pw1 = pw2 = pw3 = pw4 = 0ull;
            #pragma unroll
            for (int rr = 0; rr < 6; rr++) {
                const ulonglong2* rp = (const ulonglong2*)(rb + rr * 12);
                ulonglong2 u0 = rp[0], u1 = rp[1], u2 = rp[2], u3 = rp[3], u4 = rp[4], u5 = rp[5];
                u64 R[12] = { u0.x, u0.y, u1.x, u1.y, u2.x, u2.y,
                              u3.x, u3.y, u4.x, u4.y, u5.x, u5.y };
                if (rr >= 1) {
                    #pragma unroll
                    for (int px = 0; px < 8; px++) {
                        ffma2(acc[1][px], R[px],     pw0);
                        ffma2(acc[1][px], R[px + 1], pw1);
                        ffma2(acc[1][px], R[px + 2], pw2);
                        ffma2(acc[1][px], R[px + 3], pw3);
                        ffma2(acc[1][px], R[px + 4], pw4);
                    }
                }
                if (rr < 5) {
                    const u64* wr = wp + rr * 6;
                    ulonglong2 wa = *(const ulonglong2*)wr;
                    ulonglong2 wb = *(const ulonglong2*)(wr + 2);
                    u64 c4 = wr[4];
                    #pragma unroll
                    for (int px = 0; px < 8; px++) {
                        ffma2(acc[0][px], R[px],     wa.x);
                        ffma2(acc[0][px], R[px + 1], wa.y);
                        ffma2(acc[0][px], R[px + 2], wb.x);
                        ffma2(acc[0][px], R[px + 3], wb.y);
                        ffma2(acc[0][px], R[px + 4], c4);
                    }
                    pw0 = wa.x; pw1 = wa.y; pw2 = wb.x; pw3 = wb.y; pw4 = c4;
                }
            }
        }
    }

    int n = n0 + img;
    u64 sp = 0ull, qp = 0ull;
    float r0c0[8], r0c1[8], r1c0[8], r1c1[8];
    #pragma unroll
    for (int px = 0; px < 8; px++) {
        sp = add2(sp, acc[0][px]); ffma2(qp, acc[0][px], acc[0][px]);
        sp = add2(sp, acc[1][px]); ffma2(qp, acc[1][px], acc[1][px]);
        unpack2(acc[0][px], r0c0[px], r0c1[px]);
        unpack2(acc[1][px], r1c0[px], r1c1[px]);
    }
    float pm0[4], pn0[4], pm1[4], pn1[4];
    #pragma unroll
    for (int j = 0; j < 4; j++) {
        pm0[j] = fmaxf(fmaxf(r0c0[2 * j], r0c0[2 * j + 1]), fmaxf(r1c0[2 * j], r1c0[2 * j + 1]));
        pn0[j] = fminf(fminf(r0c0[2 * j], r0c0[2 * j + 1]), fminf(r1c0[2 * j], r1c0[2 * j + 1]));
        pm1[j] = fmaxf(fmaxf(r0c1[2 * j], r0c1[2 * j + 1]), fmaxf(r1c1[2 * j], r1c1[2 * j + 1]));
        pn1[j] = fminf(fminf(r0c1[2 * j], r0c1[2 * j + 1]), fminf(r1c1[2 * j], r1c1[2 * j + 1]));
    }
    int ob = n * 1024 + (2 * pc) * 16 + q * 4;
    *(float4*)(g_m2max + ob)      = make_float4(pm0[0], pm0[1], pm0[2], pm0[3]);
    *(float4*)(g_m2min + ob)      = make_float4(pn0[0], pn0[1], pn0[2], pn0[3]);
    *(float4*)(g_m2max + ob + 16) = make_float4(pm1[0], pm1[1], pm1[2], pm1[3]);
    *(float4*)(g_m2min + ob + 16) = make_float4(pn1[0], pn1[1], pn1[2], pn1[3]);

    #pragma unroll
    for (int off = 1; off < 4; off <<= 1) {
        sp = add2(sp, __shfl_xor_sync(0xffffffffu, sp, off));
        qp = add2(qp, __shfl_xor_sync(0xffffffffu, qp, off));
    }
    if (q == 0) {
        float s0, s1, q0, q1;
        unpack2(sp, s0, s1);
        unpack2(qp, q0, q1);
        atomicAdd(&g_sum2[2 * pc],     (double)s0);
        atomicAdd(&g_sum2[2 * pc + 1], (double)s1);
        atomicAdd(&g_sqs2[2 * pc],     (double)q0);
        atomicAdd(&g_sqs2[2 * pc + 1], (double)q1);
    }
}

// ---------------------------------------------------------------------------
// Launch 5: fc1 GEMM with fused fin2 + bnsel on A-tile load + column stats.
// ---------------------------------------------------------------------------
__global__ __launch_bounds__(256) void k_fc1(const float* __restrict__ g2, const float* __restrict__ be2) {
    __shared__ float As[16][64];
    __shared__ float Bs[16][64];
    __shared__ float scol[64], scol2[64];
    __shared__ float sA2[64], sB2[64];
    int tid = threadIdx.x;
    if (tid < 64) {
        scol[tid] = 0.f; scol2[tid] = 0.f;
        const double invM = 1.0 / (4096.0 * 64.0);
        double mean = g_sum2[tid] * invM;
        double var  = g_sqs2[tid] * invM - mean * mean;
        float A = g2[tid] * rsqrtf((float)var + 1e-5f);
        sA2[tid] = A;
        sB2[tid] = be2[tid] - (float)mean * A;
    }
    __syncthreads();

    int m0 = blockIdx.y * 64;
    int n0 = blockIdx.x * 64;
    int lr = tid >> 2;
    int lk = (tid & 3) * 4;
    const float* Amx = g_m2max + (m0 + lr) * 1024 + lk;
    const float* Amn = g_m2min + (m0 + lr) * 1024 + lk;
    const float* Bload = g_wf1q + (n0 + lr) * 1024 + lk;
    int tx = tid & 15, ty = tid >> 4;

    u64 accp[4][2];
    #pragma unroll
    for (int i = 0; i < 4; i++) { accp[i][0] = 0ull; accp[i][1] = 0ull; }

    for (int k0 = 0; k0 < 1024; k0 += 16) {
        float4 mx = *(const float4*)(Amx + k0);
        float4 mn = *(const float4*)(Amn + k0);
        float4 bv = *(const float4*)(Bload + k0);
        int c = (lk + k0) >> 4;
        float A = sA2[c], B = sB2[c];
        float4 av;
        av.x = bnsel(A, B, mx.x, mn.x);
        av.y = bnsel(A, B, mx.y, mn.y);
        av.z = bnsel(A, B, mx.z, mn.z);
        av.w = bnsel(A, B, mx.w, mn.w);
        __syncthreads();
        As[lk + 0][lr] = av.x; As[lk + 1][lr] = av.y;
        As[lk + 2][lr] = av.z; As[lk + 3][lr] = av.w;
        Bs[lk + 0][lr] = bv.x; Bs[lk + 1][lr] = bv.y;
        Bs[lk + 2][lr] = bv.z; Bs[lk + 3][lr] = bv.w;
        __syncthreads();
        #pragma unroll
        for (int k = 0; k < 16; k++) {
            float4 a = *(const float4*)&As[k][ty * 4];
            float4 b = *(const float4*)&Bs[k][tx * 4];
            u64 b01 = pack2(b.x, b.y), b23 = pack2(b.z, b.w);
            u64 a0 = rep2(a.x), a1 = rep2(a.y), a2 = rep2(a.z), a3 = rep2(a.w);
            ffma2(accp[0][0], a0, b01); ffma2(accp[0][1], a0, b23);
            ffma2(accp[1][0], a1, b01); ffma2(accp[1][1], a1, b23);
            ffma2(accp[2][0], a2, b01); ffma2(accp[2][1], a2, b23);
            ffma2(accp[3][0], a3, b01); ffma2(accp[3][1], a3, b23);
        }
    }
    float acc[4][4];
    #pragma unroll
    for (int i = 0; i < 4; i++) {
        unpack2(accp[i][0], acc[i][0], acc[i][1]);
        unpack2(accp[i][1], acc[i][2], acc[i][3]);
    }
    #pragma unroll
    for (int i = 0; i < 4; i++) {
        int row = m0 + ty * 4 + i;
        *(float4*)(g_y3 + row * 512 + n0 + tx * 4) =
            make_float4(acc[i][0], acc[i][1], acc[i][2], acc[i][3]);
    }
    #pragma unroll
    for (int j = 0; j < 4; j++) {
        float s = 0.f, q = 0.f;
        #pragma unroll
        for (int i = 0; i < 4; i++) { s += acc[i][j]; q = fmaf(acc[i][j], acc[i][j], q); }
        atomicAdd(&scol[tx * 4 + j], s);
        atomicAdd(&scol2[tx * 4 + j], q);
    }
    __syncthreads();
    if (tid < 64) {
        atomicAdd(&g_sum3[n0 + tid], (double)scol[tid]);
        atomicAdd(&g_sqs3[n0 + tid], (double)scol2[tid]);
    }
}

// ---------------------------------------------------------------------------
// Launch 6: fc2 fused with bn1d+relu. Warp per row.
// ---------------------------------------------------------------------------
__global__ __launch_bounds__(256) void k_fc2(float* __restrict__ out, const float* __restrict__ bf2,
                                             const float* __restrict__ g3, const float* __restrict__ be3) {
    __shared__ float sw[5120];
    __shared__ float sA[512], sB[512];
    __shared__ float sb[16];
    for (int i = threadIdx.x; i < 5120; i += 256) sw[i] = g_wf2q[i];
    for (int i = threadIdx.x; i < 512; i += 256) {
        const double invM = 1.0 / 4096.0;
        double mean = g_sum3[i] * invM;
        double var  = g_sqs3[i] * invM - mean * mean;
        float A = g3[i] * rsqrtf((float)var + 1e-5f);
        sA[i] = A;
        sB[i] = be3[i] - (float)mean * A;
    }
    if (threadIdx.x < 10) sb[threadIdx.x] = bf2[threadIdx.x];
    __syncthreads();

    int warp = threadIdx.x >> 5, lane = threadIdx.x & 31;
    int n = blockIdx.x * 8 + warp;
    const float* yr = g_y3 + n * 512;
    float acc[10];
    #pragma unroll
    for (int o = 0; o < 10; o++) acc[o] = 0.f;
    for (int f = lane; f < 512; f += 32) {
        float a = fmaxf(fmaf(sA[f], yr[f], sB[f]), 0.f);
        #pragma unroll
        for (int o = 0; o < 10; o++) acc[o] = fmaf(a, sw[o * 512 + f], acc[o]);
    }
    #pragma unroll
    for (int o = 0; o < 10; o++) {
        float s = acc[o];
        #pragma unroll
        for (int off = 16; off; off >>= 1) s += __shfl_xor_sync(0xffffffffu, s, off);
        if (lane == 0) out[n * 10 + o] = s + sb[o];
    }
}

// ---------------------------------------------------------------------------
extern "C" void kernel_launch(void* const* d_in, const int* in_sizes, int n_in,
                              void* d_out, int out_size) {
    const float* x   = (const float*)d_in[0];
    const float* w1  = (const float*)d_in[1];
    const float* g1  = (const float*)d_in[3];
    const float* be1 = (const float*)d_in[4];
    const float* w2  = (const float*)d_in[5];
    const float* g2  = (const float*)d_in[7];
    const float* be2 = (const float*)d_in[8];
    const float* wf1 = (const float*)d_in[9];
    const float* g3  = (const float*)d_in[11];
    const float* be3 = (const float*)d_in[12];
    const float* wf2 = (const float*)d_in[13];
    const float* bf2 = (const float*)d_in[14];
    float* out = (float*)d_out;

    const int conv2_smem = (9216 + 3840) * 8;   // 104448 B dynamic
    cudaFuncSetAttribute(k_conv2, cudaFuncAttributeMaxDynamicSharedMemorySize, conv2_smem);

    k_absmax<<<96, 256>>>(w1, w2, wf1, wf2);        // 1
    k_conv1<<<4096, 192>>>(x, w1, w2, wf1, wf2);    // 2
    k_fin1<<<1, 32>>>(g1, be1);                     // 3
    k_conv2<<<2048, 256, conv2_smem>>>();           // 4  <- profiled
    dim3 g_fc1(8, 64);
    k_fc1<<<g_fc1, 256>>>(g2, be2);                 // 5
    k_fc2<<<512, 256>>>(out, bf2, g3, be3);         // 6
}

// round 8
// speedup vs baseline: 1.7687x; 1.7687x over previous
#include <cuda_runtime.h>

// ---------------------------------------------------------------------------
// MNIST TWN CNN forward, batch 4096, fp32.
// R8: conv2 reverted to R6's proven config (scalar smem input, rep2 in regs,
//     per-ci weight double buffer). fc1 keeps R7's fused fin2+bnsel A-load.
// Launches: absmax, conv1, fin1, conv2(#4 profiled), fc1, fc2.
// ---------------------------------------------------------------------------

#define NIMG 4096
typedef unsigned long long u64;

__device__ __forceinline__ u64 pack2(float lo, float hi) {
    u64 r; asm("mov.b64 %0,{%1,%2};" : "=l"(r) : "f"(lo), "f"(hi)); return r;
}
__device__ __forceinline__ u64 rep2(float v) { return pack2(v, v); }
__device__ __forceinline__ void unpack2(u64 p, float& lo, float& hi) {
    asm("mov.b64 {%0,%1},%2;" : "=f"(lo), "=f"(hi) : "l"(p));
}
__device__ __forceinline__ void ffma2(u64& d, u64 a, u64 b) {
    asm("fma.rn.f32x2 %0,%1,%2,%0;" : "+l"(d) : "l"(a), "l"(b));
}
__device__ __forceinline__ u64 add2(u64 a, u64 b) {
    u64 r; asm("add.rn.f32x2 %0,%1,%2;" : "=l"(r) : "l"(a), "l"(b)); return r;
}
__device__ __forceinline__ float ternary(float w, float t) {
    return (w > t ? 1.0f : 0.0f) - (w < -t ? 1.0f : 0.0f);
}
__device__ __forceinline__ float bnsel(float A, float B, float mx, float mn) {
    return fmaxf(A > 0.f ? fmaf(A, mx, B) : fmaf(A, mn, B), 0.f);
}

// ---- device scratch (static only) -----------------------------------------
static __device__ u64   g_w2p[32 * 800];         // [ci][pc][25] channel-pair packed
static __device__ float g_wf1q[512 * 1024];
static __device__ float g_wf2q[10 * 512];
static __device__ float g_pmax[96][4];

static __device__ double g_sum1[32],  g_sqs1[32];
static __device__ double g_sum2[64],  g_sqs2[64];
static __device__ double g_sum3[512], g_sqs3[512];

static __device__ float g_sc1[32], g_sh1[32];

static __device__ float g_m1max[NIMG * 32 * 144];
static __device__ float g_m1min[NIMG * 32 * 144];
static __device__ float g_m2max[NIMG * 1024];
static __device__ float g_m2min[NIMG * 1024];
static __device__ float g_y3[NIMG * 512];

// ---------------------------------------------------------------------------
// Launch 1: abs-max partials (grid MUST be 96). Block 0 zeros stat accums.
// ---------------------------------------------------------------------------
__global__ __launch_bounds__(256) void k_absmax(const float* __restrict__ w1, const float* __restrict__ w2,
                                                const float* __restrict__ wf1, const float* __restrict__ wf2) {
    __shared__ float sm[8][4];
    int tid = threadIdx.x;
    if (blockIdx.x == 0) {
        if (tid < 32) { g_sum1[tid] = 0.0; g_sqs1[tid] = 0.0; }
        if (tid < 64) { g_sum2[tid] = 0.0; g_sqs2[tid] = 0.0; }
        g_sum3[tid] = 0.0;       g_sqs3[tid] = 0.0;
        g_sum3[tid + 256] = 0.0; g_sqs3[tid + 256] = 0.0;
    }
    int gid = blockIdx.x * 256 + tid;
    int stride = 96 * 256;
    float m0 = 0.f, m1 = 0.f, m2 = 0.f, m3 = 0.f;
    for (int i = gid; i < 800;    i += stride) m0 = fmaxf(m0, fabsf(w1[i]));
    for (int i = gid; i < 51200;  i += stride) m1 = fmaxf(m1, fabsf(w2[i]));
    for (int i = gid; i < 524288; i += stride) m2 = fmaxf(m2, fabsf(wf1[i]));
    for (int i = gid; i < 5120;   i += stride) m3 = fmaxf(m3, fabsf(wf2[i]));
    #pragma unroll
    for (int off = 16; off; off >>= 1) {
        m0 = fmaxf(m0, __shfl_xor_sync(0xffffffffu, m0, off));
        m1 = fmaxf(m1, __shfl_xor_sync(0xffffffffu, m1, off));
        m2 = fmaxf(m2, __shfl_xor_sync(0xffffffffu, m2, off));
        m3 = fmaxf(m3, __shfl_xor_sync(0xffffffffu, m3, off));
    }
    int w = tid >> 5;
    if ((tid & 31) == 0) { sm[w][0] = m0; sm[w][1] = m1; sm[w][2] = m2; sm[w][3] = m3; }
    __syncthreads();
    if (tid == 0) {
        float r0 = 0.f, r1 = 0.f, r2 = 0.f, r3 = 0.f;
        #pragma unroll
        for (int i = 0; i < 8; i++) {
            r0 = fmaxf(r0, sm[i][0]); r1 = fmaxf(r1, sm[i][1]);
            r2 = fmaxf(r2, sm[i][2]); r3 = fmaxf(r3, sm[i][3]);
        }
        g_pmax[blockIdx.x][0] = r0; g_pmax[blockIdx.x][1] = r1;
        g_pmax[blockIdx.x][2] = r2; g_pmax[blockIdx.x][3] = r3;
    }
}

// ---------------------------------------------------------------------------
// Launch 2: conv1 + stats + pooled max/min. One block/image, 192 threads.
// ---------------------------------------------------------------------------
__global__ __launch_bounds__(192) void k_conv1(const float* __restrict__ x,  const float* __restrict__ w1,
                                               const float* __restrict__ w2, const float* __restrict__ wf1,
                                               const float* __restrict__ wf2) {
    __shared__ u64 sx[784];
    __shared__ u64 sw1[400];
    __shared__ float sthr[4];
    __shared__ float ssum[32], ssq[32];
    int tid = threadIdx.x, n = blockIdx.x;

    if (tid < 4) {
        float m = 0.f;
        #pragma unroll 8
        for (int i = 0; i < 96; i++) m = fmaxf(m, g_pmax[i][tid]);
        sthr[tid] = 0.05f * m;
    }
    if (tid < 32) { ssum[tid] = 0.f; ssq[tid] = 0.f; }
    __syncthreads();

    for (int i = tid; i < 400; i += 192) {
        int cp = i / 25, k = i - cp * 25;
        float t0 = sthr[0];
        sw1[i] = pack2(ternary(w1[(2 * cp) * 25 + k], t0),
                       ternary(w1[(2 * cp + 1) * 25 + k], t0));
    }
    for (int i = tid; i < 784; i += 192) sx[i] = rep2(x[n * 784 + i]);

    {   // distributed quantization ([ci][pc][25] conv2 layout)
        int gu = n * 192 + tid;
        if (gu < 25600) {
            int ci = gu / 800, r = gu - ci * 800;
            int pc = r / 25, k = r - pc * 25;
            float t1 = sthr[1];
            ((float2*)g_w2p)[gu] = make_float2(ternary(w2[(2 * pc) * 800 + ci * 25 + k], t1),
                                               ternary(w2[(2 * pc + 1) * 800 + ci * 25 + k], t1));
        } else if (gu < 25600 + 524288) {
            g_wf1q[gu - 25600] = ternary(wf1[gu - 25600], sthr[2]);
        } else if (gu < 25600 + 524288 + 5120) {
            g_wf2q[gu - 549888] = ternary(wf2[gu - 549888], sthr[3]);
        }
    }
    __syncthreads();

    int cp = tid / 12;
    int q  = tid - cp * 12;
    const u64* wbase = sw1 + cp * 25;
    u64 sp = 0ull, qp = 0ull;
    float* pmx0 = g_m1max + n * 4608 + (2 * cp) * 144 + q * 12;
    float* pmn0 = g_m1min + n * 4608 + (2 * cp) * 144 + q * 12;

    #pragma unroll
    for (int ob = 0; ob < 24; ob += 4) {
        u64 a0[4] = {0ull, 0ull, 0ull, 0ull};
        u64 a1[4] = {0ull, 0ull, 0ull, 0ull};
        u64 pw0, pw1, pw2, pw3, pw4;
        pw0 = pw1 = pw2 = pw3 = pw4 = 0ull;
        #pragma unroll
        for (int rr = 0; rr < 6; rr++) {
            const ulonglong2* xr = (const ulonglong2*)(sx + (2 * q + rr) * 28 + ob);
            ulonglong2 v0 = xr[0], v1 = xr[1], v2 = xr[2], v3 = xr[3];
            u64 X[8] = { v0.x, v0.y, v1.x, v1.y, v2.x, v2.y, v3.x, v3.y };
            if (rr >= 1) {
                #pragma unroll
                for (int o = 0; o < 4; o++) {
                    ffma2(a1[o], X[o],     pw0);
                    ffma2(a1[o], X[o + 1], pw1);
                    ffma2(a1[o], X[o + 2], pw2);
                    ffma2(a1[o], X[o + 3], pw3);
                    ffma2(a1[o], X[o + 4], pw4);
                }
            }
            if (rr < 5) {
                const u64* wr = wbase + rr * 5;
                u64 c0 = wr[0], c1 = wr[1], c2 = wr[2], c3 = wr[3], c4 = wr[4];
                #pragma unroll
                for (int o = 0; o < 4; o++) {
                    ffma2(a0[o], X[o],     c0);
                    ffma2(a0[o], X[o + 1], c1);
                    ffma2(a0[o], X[o + 2], c2);
                    ffma2(a0[o], X[o + 3], c3);
                    ffma2(a0[o], X[o + 4], c4);
                }
                pw0 = c0; pw1 = c1; pw2 = c2; pw3 = c3; pw4 = c4;
            }
        }
        float r0c0[4], r0c1[4], r1c0[4], r1c1[4];
        #pragma unroll
        for (int o = 0; o < 4; o++) {
            sp = add2(sp, a0[o]); ffma2(qp, a0[o], a0[o]);
            sp = add2(sp, a1[o]); ffma2(qp, a1[o], a1[o]);
            unpack2(a0[o], r0c0[o], r0c1[o]);
            unpack2(a1[o], r1c0[o], r1c1[o]);
        }
        float mx0[2], mn0[2], mx1[2], mn1[2];
        #pragma unroll
        for (int j = 0; j < 2; j++) {
            float A0 = r0c0[2 * j], B0 = r0c0[2 * j + 1], C0 = r1c0[2 * j], D0 = r1c0[2 * j + 1];
            mx0[j] = fmaxf(fmaxf(A0, B0), fmaxf(C0, D0));
            mn0[j] = fminf(fminf(A0, B0), fminf(C0, D0));
            float A1 = r0c1[2 * j], B1 = r0c1[2 * j + 1], C1 = r1c1[2 * j], D1 = r1c1[2 * j + 1];
            mx1[j] = fmaxf(fmaxf(A1, B1), fmaxf(C1, D1));
            mn1[j] = fminf(fminf(A1, B1), fminf(C1, D1));
        }
        int pc2 = ob >> 1;
        *(float2*)(pmx0 + pc2)       = make_float2(mx0[0], mx0[1]);
        *(float2*)(pmn0 + pc2)       = make_float2(mn0[0], mn0[1]);
        *(float2*)(pmx0 + 144 + pc2) = make_float2(mx1[0], mx1[1]);
        *(float2*)(pmn0 + 144 + pc2) = make_float2(mn1[0], mn1[1]);
    }
    float s0, s1, q0, q1;
    unpack2(sp, s0, s1);
    unpack2(qp, q0, q1);
    atomicAdd(&ssum[2 * cp],     s0);
    atomicAdd(&ssum[2 * cp + 1], s1);
    atomicAdd(&ssq[2 * cp],      q0);
    atomicAdd(&ssq[2 * cp + 1],  q1);
    __syncthreads();
    if (tid < 32) {
        atomicAdd(&g_sum1[tid], (double)ssum[tid]);
        atomicAdd(&g_sqs1[tid], (double)ssq[tid]);
    }
}

// ---------------------------------------------------------------------------
// Launch 3: finalize layer-1 BN affine.
// ---------------------------------------------------------------------------
__global__ void k_fin1(const float* __restrict__ g, const float* __restrict__ be) {
    int i = threadIdx.x;
    if (i >= 32) return;
    const double invM = 1.0 / (4096.0 * 576.0);
    double mean = g_sum1[i] * invM;
    double var  = g_sqs1[i] * invM - mean * mean;
    float A = g[i] * rsqrtf((float)var + 1e-5f);
    g_sc1[i] = A;
    g_sh1[i] = be[i] - (float)mean * A;
}

// ---------------------------------------------------------------------------
// Launch 4 (PROFILED): conv2 — R6 proven config. Scalar smem input (bnsel
// applied on staging), rep2 in registers, per-ci weight double buffer.
// 2 images/CTA, 256 thr = 2img x 32pc x 4 rowpairs.
// ---------------------------------------------------------------------------
__global__ __launch_bounds__(256) void k_conv2() {
    __shared__ float sin_[2][4608];            // 36.9 KB scalar input
    __shared__ u64 swt[2][800];                // 12.8 KB weight double buffer
    __shared__ float sA1[32], sB1[32];
    int tid = threadIdx.x;
    int n0 = blockIdx.x * 2;

    if (tid < 32) { sA1[tid] = g_sc1[tid]; sB1[tid] = g_sh1[tid]; }
    __syncthreads();

    {   // staged load with fused bn+relu+pool-select
        const float4* mx4 = (const float4*)(g_m1max + n0 * 4608);
        const float4* mn4 = (const float4*)(g_m1min + n0 * 4608);
        float4* s4 = (float4*)sin_;
        for (int i = tid; i < 2304; i += 256) {
            int c = (i % 1152) / 36;
            float A = sA1[c], B = sB1[c];
            float4 mx = mx4[i], mn = mn4[i];
            float4 v;
            v.x = bnsel(A, B, mx.x, mn.x);
            v.y = bnsel(A, B, mx.y, mn.y);
            v.z = bnsel(A, B, mx.z, mn.z);
            v.w = bnsel(A, B, mx.w, mn.w);
            s4[i] = v;
        }
    }
    for (int j = tid; j < 800; j += 256) swt[0][j] = g_w2p[j];
    __syncthreads();

    int img = tid >> 7;
    int t   = tid & 127;
    int pc  = t >> 2;
    int q   = t & 3;
    const float* ib = sin_[img] + q * 24;

    u64 acc[2][8];
    #pragma unroll
    for (int oy = 0; oy < 2; oy++)
        #pragma unroll
        for (int px = 0; px < 8; px++) acc[oy][px] = 0ull;

    for (int ci = 0; ci < 32; ci++) {
        if (ci < 31) {
            const u64* ws = g_w2p + (ci + 1) * 800;
            for (int j = tid; j < 800; j += 256) swt[(ci + 1) & 1][j] = ws[j];
        }
        const u64* wp = swt[ci & 1] + pc * 25;
        const float* rb = ib + ci * 144;
        u64 pw0, pw1, pw2, pw3, pw4;
        pw0 = pw1 = pw2 = pw3 = pw4 = 0ull;
        #pragma unroll
        for (int rr = 0; rr < 6; rr++) {
            float4 f0 = *(const float4*)(rb + rr * 12);
            float4 f1 = *(const float4*)(rb + rr * 12 + 4);
            float4 f2 = *(const float4*)(rb + rr * 12 + 8);
            u64 R[12] = { rep2(f0.x), rep2(f0.y), rep2(f0.z), rep2(f0.w),
                          rep2(f1.x), rep2(f1.y), rep2(f1.z), rep2(f1.w),
                          rep2(f2.x), rep2(f2.y), rep2(f2.z), rep2(f2.w) };
            if (rr >= 1) {
                #pragma unroll
                for (int px = 0; px < 8; px++) {
                    ffma2(acc[1][px], R[px],     pw0);
                    ffma2(acc[1][px], R[px + 1], pw1);
                    ffma2(acc[1][px], R[px + 2], pw2);
                    ffma2(acc[1][px], R[px + 3], pw3);
                    ffma2(acc[1][px], R[px + 4], pw4);
                }
            }
            if (rr < 5) {
                const u64* wr = wp + rr * 5;
                u64 c0 = wr[0], c1 = wr[1], c2 = wr[2], c3 = wr[3], c4 = wr[4];
                #pragma unroll
                for (int px = 0; px < 8; px++) {
                    ffma2(acc[0][px], R[px],     c0);
                    ffma2(acc[0][px], R[px + 1], c1);
                    ffma2(acc[0][px], R[px + 2], c2);
                    ffma2(acc[0][px], R[px + 3], c3);
                    ffma2(acc[0][px], R[px + 4], c4);
                }
                pw0 = c0; pw1 = c1; pw2 = c2; pw3 = c3; pw4 = c4;
            }
        }
        __syncthreads();
    }

    int n = n0 + img;
    u64 sp = 0ull, qp = 0ull;
    float r0c0[8], r0c1[8], r1c0[8], r1c1[8];
    #pragma unroll
    for (int px = 0; px < 8; px++) {
        sp = add2(sp, acc[0][px]); ffma2(qp, acc[0][px], acc[0][px]);
        sp = add2(sp, acc[1][px]); ffma2(qp, acc[1][px], acc[1][px]);
        unpack2(acc[0][px], r0c0[px], r0c1[px]);
        unpack2(acc[1][px], r1c0[px], r1c1[px]);
    }
    float pm0[4], pn0[4], pm1[4], pn1[4];
    #pragma unroll
    for (int j = 0; j < 4; j++) {
        pm0[j] = fmaxf(fmaxf(r0c0[2 * j], r0c0[2 * j + 1]), fmaxf(r1c0[2 * j], r1c0[2 * j + 1]));
        pn0[j] = fminf(fminf(r0c0[2 * j], r0c0[2 * j + 1]), fminf(r1c0[2 * j], r1c0[2 * j + 1]));
        pm1[j] = fmaxf(fmaxf(r0c1[2 * j], r0c1[2 * j + 1]), fmaxf(r1c1[2 * j], r1c1[2 * j + 1]));
        pn1[j] = fminf(fminf(r0c1[2 * j], r0c1[2 * j + 1]), fminf(r1c1[2 * j], r1c1[2 * j + 1]));
    }
    int ob = n * 1024 + (2 * pc) * 16 + q * 4;
    *(float4*)(g_m2max + ob)      = make_float4(pm0[0], pm0[1], pm0[2], pm0[3]);
    *(float4*)(g_m2min + ob)      = make_float4(pn0[0], pn0[1], pn0[2], pn0[3]);
    *(float4*)(g_m2max + ob + 16) = make_float4(pm1[0], pm1[1], pm1[2], pm1[3]);
    *(float4*)(g_m2min + ob + 16) = make_float4(pn1[0], pn1[1], pn1[2], pn1[3]);

    #pragma unroll
    for (int off = 1; off < 4; off <<= 1) {
        sp = add2(sp, __shfl_xor_sync(0xffffffffu, sp, off));
        qp = add2(qp, __shfl_xor_sync(0xffffffffu, qp, off));
    }
    if (q == 0) {
        float s0, s1, q0, q1;
        unpack2(sp, s0, s1);
        unpack2(qp, q0, q1);
        atomicAdd(&g_sum2[2 * pc],     (double)s0);
        atomicAdd(&g_sum2[2 * pc + 1], (double)s1);
        atomicAdd(&g_sqs2[2 * pc],     (double)q0);
        atomicAdd(&g_sqs2[2 * pc + 1], (double)q1);
    }
}

// ---------------------------------------------------------------------------
// Launch 5: fc1 GEMM with fused fin2 + bnsel on A-tile load + column stats.
// ---------------------------------------------------------------------------
__global__ __launch_bounds__(256) void k_fc1(const float* __restrict__ g2, const float* __restrict__ be2) {
    __shared__ float As[16][64];
    __shared__ float Bs[16][64];
    __shared__ float scol[64], scol2[64];
    __shared__ float sA2[64], sB2[64];
    int tid = threadIdx.x;
    if (tid < 64) {
        scol[tid] = 0.f; scol2[tid] = 0.f;
        const double invM = 1.0 / (4096.0 * 64.0);
        double mean = g_sum2[tid] * invM;
        double var  = g_sqs2[tid] * invM - mean * mean;
        float A = g2[tid] * rsqrtf((float)var + 1e-5f);
        sA2[tid] = A;
        sB2[tid] = be2[tid] - (float)mean * A;
    }
    __syncthreads();

    int m0 = blockIdx.y * 64;
    int n0 = blockIdx.x * 64;
    int lr = tid >> 2;
    int lk = (tid & 3) * 4;
    const float* Amx = g_m2max + (m0 + lr) * 1024 + lk;
    const float* Amn = g_m2min + (m0 + lr) * 1024 + lk;
    const float* Bload = g_wf1q + (n0 + lr) * 1024 + lk;
    int tx = tid & 15, ty = tid >> 4;

    u64 accp[4][2];
    #pragma unroll
    for (int i = 0; i < 4; i++) { accp[i][0] = 0ull; accp[i][1] = 0ull; }

    for (int k0 = 0; k0 < 1024; k0 += 16) {
        float4 mx = *(const float4*)(Amx + k0);
        float4 mn = *(const float4*)(Amn + k0);
        float4 bv = *(const float4*)(Bload + k0);
        int c = (lk + k0) >> 4;
        float A = sA2[c], B = sB2[c];
        float4 av;
        av.x = bnsel(A, B, mx.x, mn.x);
        av.y = bnsel(A, B, mx.y, mn.y);
        av.z = bnsel(A, B, mx.z, mn.z);
        av.w = bnsel(A, B, mx.w, mn.w);
        __syncthreads();
        As[lk + 0][lr] = av.x; As[lk + 1][lr] = av.y;
        As[lk + 2][lr] = av.z; As[lk + 3][lr] = av.w;
        Bs[lk + 0][lr] = bv.x; Bs[lk + 1][lr] = bv.y;
        Bs[lk + 2][lr] = bv.z; Bs[lk + 3][lr] = bv.w;
        __syncthreads();
        #pragma unroll
        for (int k = 0; k < 16; k++) {
            float4 a = *(const float4*)&As[k][ty * 4];
            float4 b = *(const float4*)&Bs[k][tx * 4];
            u64 b01 = pack2(b.x, b.y), b23 = pack2(b.z, b.w);
            u64 a0 = rep2(a.x), a1 = rep2(a.y), a2 = rep2(a.z), a3 = rep2(a.w);
            ffma2(accp[0][0], a0, b01); ffma2(accp[0][1], a0, b23);
            ffma2(accp[1][0], a1, b01); ffma2(accp[1][1], a1, b23);
            ffma2(accp[2][0], a2, b01); ffma2(accp[2][1], a2, b23);
            ffma2(accp[3][0], a3, b01); ffma2(accp[3][1], a3, b23);
        }
    }
    float acc[4][4];
    #pragma unroll
    for (int i = 0; i < 4; i++) {
        unpack2(accp[i][0], acc[i][0], acc[i][1]);
        unpack2(accp[i][1], acc[i][2], acc[i][3]);
    }
    #pragma unroll
    for (int i = 0; i < 4; i++) {
        int row = m0 + ty * 4 + i;
        *(float4*)(g_y3 + row * 512 + n0 + tx * 4) =
            make_float4(acc[i][0], acc[i][1], acc[i][2], acc[i][3]);
    }
    #pragma unroll
    for (int j = 0; j < 4; j++) {
        float s = 0.f, q = 0.f;
        #pragma unroll
        for (int i = 0; i < 4; i++) { s += acc[i][j]; q = fmaf(acc[i][j], acc[i][j], q); }
        atomicAdd(&scol[tx * 4 + j], s);
        atomicAdd(&scol2[tx * 4 + j], q);
    }
    __syncthreads();
    if (tid < 64) {
        atomicAdd(&g_sum3[n0 + tid], (double)scol[tid]);
        atomicAdd(&g_sqs3[n0 + tid], (double)scol2[tid]);
    }
}

// ---------------------------------------------------------------------------
// Launch 6: fc2 fused with bn1d+relu. Warp per row.
// ---------------------------------------------------------------------------
__global__ __launch_bounds__(256) void k_fc2(float* __restrict__ out, const float* __restrict__ bf2,
                                             const float* __restrict__ g3, const float* __restrict__ be3) {
    __shared__ float sw[5120];
    __shared__ float sA[512], sB[512];
    __shared__ float sb[16];
    for (int i = threadIdx.x; i < 5120; i += 256) sw[i] = g_wf2q[i];
    for (int i = threadIdx.x; i < 512; i += 256) {
        const double invM = 1.0 / 4096.0;
        double mean = g_sum3[i] * invM;
        double var  = g_sqs3[i] * invM - mean * mean;
        float A = g3[i] * rsqrtf((float)var + 1e-5f);
        sA[i] = A;
        sB[i] = be3[i] - (float)mean * A;
    }
    if (threadIdx.x < 10) sb[threadIdx.x] = bf2[threadIdx.x];
    __syncthreads();

    int warp = threadIdx.x >> 5, lane = threadIdx.x & 31;
    int n = blockIdx.x * 8 + warp;
    const float* yr = g_y3 + n * 512;
    float acc[10];
    #pragma unroll
    for (int o = 0; o < 10; o++) acc[o] = 0.f;
    for (int f = lane; f < 512; f += 32) {
        float a = fmaxf(fmaf(sA[f], yr[f], sB[f]), 0.f);
        #pragma unroll
        for (int o = 0; o < 10; o++) acc[o] = fmaf(a, sw[o * 512 + f], acc[o]);
    }
    #pragma unroll
    for (int o = 0; o < 10; o++) {
        float s = acc[o];
        #pragma unroll
        for (int off = 16; off; off >>= 1) s += __shfl_xor_sync(0xffffffffu, s, off);
        if (lane == 0) out[n * 10 + o] = s + sb[o];
    }
}

// ---------------------------------------------------------------------------
extern "C" void kernel_launch(void* const* d_in, const int* in_sizes, int n_in,
                              void* d_out, int out_size) {
    const float* x   = (const float*)d_in[0];
    const float* w1  = (const float*)d_in[1];
    const float* g1  = (const float*)d_in[3];
    const float* be1 = (const float*)d_in[4];
    const float* w2  = (const float*)d_in[5];
    const float* g2  = (const float*)d_in[7];
    const float* be2 = (const float*)d_in[8];
    const float* wf1 = (const float*)d_in[9];
    const float* g3  = (const float*)d_in[11];
    const float* be3 = (const float*)d_in[12];
    const float* wf2 = (const float*)d_in[13];
    const float* bf2 = (const float*)d_in[14];
    float* out = (float*)d_out;

    k_absmax<<<96, 256>>>(w1, w2, wf1, wf2);        // 1
    k_conv1<<<4096, 192>>>(x, w1, w2, wf1, wf2);    // 2
    k_fin1<<<1, 32>>>(g1, be1);                     // 3
    k_conv2<<<2048, 256>>>();                       // 4  <- profiled
    dim3 g_fc1(8, 64);
    k_fc1<<<g_fc1, 256>>>(g2, be2);                 // 5
    k_fc2<<<512, 256>>>(out, bf2, g3, be3);         // 6
}